// round 6
// baseline (speedup 1.0000x reference)
#include <cuda_runtime.h>
#include <math.h>
#include <stdint.h>

// Problem dims (fixed)
#define SEQ 256
#define BATCH 32
#define EDIM 256
#define HDIM 512
#define GDIM 2048           // 4*H
#define TTAGS 10
#define START_TAG 8
#define STOP_TAG 9
#define NEGV -10000.0f

#define NBLK 128            // recurrent persistent blocks (64 per direction)

// packed fp32x2 helpers (sm_103a native; ptxas never emits from C++)
#define FMA2(acc, a, b) asm("fma.rn.f32x2 %0, %1, %2, %3;" : "=l"(acc) : "l"(a), "l"(b), "l"(acc))
#define SPLAT2(d, s)    asm("mov.b64 %0, {%1, %1};" : "=l"(d) : "f"(s))
#define UNPK2(lo, hi, s) asm("mov.b64 {%0, %1}, %2;" : "=f"(lo), "=f"(hi) : "l"(s))

// ---------------- scratch (static device globals; no runtime alloc) ----------
// TRANSPOSED pre-activations: [d][n][m], n = gate*512+j (2048), m = t*32+b (8192)
__device__ float g_xgT[2u * GDIM * (SEQ * BATCH)];
__device__ float g_hseq[2u * SEQ * BATCH * HDIM];      // all hidden states [d][t][b][j]
__device__ float g_hzero[BATCH * HDIM];                // never written -> stays zero
__device__ float g_feats[SEQ * BATCH * TTAGS];         // emissions
__device__ int   g_arrive[NBLK];                       // per-block arrival epochs
__device__ int   g_rel[64];                            // release words: [0]=dir0, [32]=dir1

__device__ __forceinline__ uint32_t smem_u32(const void* p) {
    uint32_t a;
    asm("{ .reg .u64 t; cvta.to.shared.u64 t, %1; cvt.u32.u64 %0, t; }" : "=r"(a) : "l"(p));
    return a;
}

__device__ __forceinline__ void mbar_wait(uint32_t addr, uint32_t par) {
    asm volatile(
        "{\n\t.reg .pred P;\n"
        "LW_%=:\n\t"
        "mbarrier.try_wait.parity.acquire.cta.shared::cta.b64 P, [%0], %1, 0x989680;\n\t"
        "@P bra LD_%=;\n\t"
        "bra LW_%=;\n"
        "LD_%=:\n\t}"
        :: "r"(addr), "r"(par) : "memory");
}

// ---------------------------------------------------------------------------
// Kernel 1: xgT[d][n][m] = sum_e emb[tok[m]][e] * w_ih_d[n][e] + b_d[n]
// BM=128 (m=(t,b)), BN=128, BK=16, 256 thr, 8x8 microtile (fp32x2 along m).
// Output stored TRANSPOSED [n][m] via smem tile transpose (coalesced STG).
// ---------------------------------------------------------------------------
__global__ void __launch_bounds__(256) xg_kernel(
    const int* __restrict__ tokens, const float* __restrict__ emb,
    const float* __restrict__ wf, const float* __restrict__ bf,
    const float* __restrict__ wb, const float* __restrict__ bb)
{
    const int bm = blockIdx.x;          // 64
    const int bn = blockIdx.y;          // 16
    const int dir = blockIdx.z;         // 2
    const int tid = threadIdx.x;

    const float* w    = dir ? wb : wf;
    const float* bias = dir ? bb : bf;

    __shared__ int   rowtok[128];
    __shared__ __align__(16) float sh[4352];  // As(2112)+Bs(2112) in GEMM; Ts(32*136) after
    float* As = sh;
    float* Bs = sh + 2112;

    if (tid < 128) {
        int mg = bm * 128 + tid;                 // m = t*32 + b
        rowtok[tid] = tokens[(mg & 31) * SEQ + (mg >> 5)];
    }
    __syncthreads();

    const int ty = tid >> 4;   // 0..15 -> 8 rows (m)
    const int tx = tid & 15;   // 0..15 -> 8 cols (n)

    uint64_t acc[4][8];        // [m-pair][n], packed f32x2 along m
    #pragma unroll
    for (int i = 0; i < 4; i++)
        #pragma unroll
        for (int j = 0; j < 8; j++) acc[i][j] = 0ull;

    for (int k0 = 0; k0 < EDIM; k0 += 16) {
        #pragma unroll
        for (int it = 0; it < 2; ++it) {
            int f4 = tid + it * 256;
            int m = f4 >> 2, kq = f4 & 3;
            float4 v = *(const float4*)(emb + (size_t)rowtok[m] * EDIM + k0 + kq * 4);
            As[(kq * 4 + 0) * 132 + m] = v.x;
            As[(kq * 4 + 1) * 132 + m] = v.y;
            As[(kq * 4 + 2) * 132 + m] = v.z;
            As[(kq * 4 + 3) * 132 + m] = v.w;
        }
        #pragma unroll
        for (int it = 0; it < 2; ++it) {
            int f4 = tid + it * 256;
            int n = f4 >> 2, kq = f4 & 3;
            float4 v = *(const float4*)(w + (size_t)(bn * 128 + n) * EDIM + k0 + kq * 4);
            Bs[(kq * 4 + 0) * 132 + n] = v.x;
            Bs[(kq * 4 + 1) * 132 + n] = v.y;
            Bs[(kq * 4 + 2) * 132 + n] = v.z;
            Bs[(kq * 4 + 3) * 132 + n] = v.w;
        }
        __syncthreads();
        #pragma unroll
        for (int k = 0; k < 16; k++) {
            ulonglong2 a0 = *(const ulonglong2*)(As + k * 132 + ty * 8);
            ulonglong2 a1 = *(const ulonglong2*)(As + k * 132 + ty * 8 + 4);
            float4 b0 = *(const float4*)(Bs + k * 132 + tx * 8);
            float4 b1 = *(const float4*)(Bs + k * 132 + tx * 8 + 4);
            float bv[8] = {b0.x, b0.y, b0.z, b0.w, b1.x, b1.y, b1.z, b1.w};
            uint64_t a2[4] = {a0.x, a0.y, a1.x, a1.y};
            #pragma unroll
            for (int j = 0; j < 8; j++) {
                uint64_t bs; SPLAT2(bs, bv[j]);
                FMA2(acc[0][j], a2[0], bs);
                FMA2(acc[1][j], a2[1], bs);
                FMA2(acc[2][j], a2[2], bs);
                FMA2(acc[3][j], a2[3], bs);
            }
        }
        __syncthreads();
    }

    float bb8[8];
    #pragma unroll
    for (int j = 0; j < 8; j++) bb8[j] = bias[bn * 128 + tx * 8 + j];

    // ---- transpose through smem, store coalesced to g_xgT[n][m] ----
    // Row stride 136 floats (multiple of 4 -> float4-aligned reads).
    float* Ts = sh;                         // 32 rows x stride 136 = 4352 floats
    for (int jp = 0; jp < 4; jp++) {
        __syncthreads();
        #pragma unroll
        for (int jj = 0; jj < 2; jj++) {
            int j = jp * 2 + jj;
            int rn = tx * 2 + jj;
            #pragma unroll
            for (int mp = 0; mp < 4; mp++) {
                float lo, hi; UNPK2(lo, hi, acc[mp][j]);
                float2 v = make_float2(lo + bb8[j], hi + bb8[j]);
                *(float2*)(Ts + rn * 136 + ty * 8 + mp * 2) = v;
            }
        }
        __syncthreads();
        // read coalesced: 1024 float4 = 256 thr x 4
        #pragma unroll
        for (int i = 0; i < 4; i++) {
            int f = tid + i * 256;          // float4 index in [0,1024)
            int rn = f >> 5, mq = f & 31;
            float4 v = *(const float4*)(Ts + rn * 136 + mq * 4);
            int n_local = (rn >> 1) * 8 + jp * 2 + (rn & 1);
            size_t n = (size_t)(dir * GDIM + bn * 128 + n_local);
            *(float4*)(g_xgT + n * 8192 + bm * 128 + mq * 4) = v;
        }
    }
}

// ---------------------------------------------------------------------------
// Kernel 2: persistent bidirectional LSTM recurrence.
// 128 blocks x 256 thr. Block = (dir, 8 hidden units -> 32 gate rows).
// W_hh in registers (f32x2). h_prev staged via 4 pipelined TMA bulk copies.
// Flag-based per-direction grid barrier. xg reads coalesced from g_xgT,
// issued BEFORE the barrier so DRAM latency overlaps the wait.
// ---------------------------------------------------------------------------
__global__ void __launch_bounds__(256, 1) recur_kernel(
    const float* __restrict__ whhf, const float* __restrict__ whhb)
{
    extern __shared__ float dsm[];
    float* stage = dsm;                 // 16384 floats: h_prev [32][512] contiguous
    float* part  = dsm + 16384;         // 8*32*33 floats
    __shared__ __align__(8) uint64_t mbars[4];

    const int tid = threadIdx.x;
    const int bid = blockIdx.x;
    const int dir   = bid >> 6;
    const int chunk = bid & 63;
    const int j0    = chunk * 8;
    // GEMM role
    const int kc = tid >> 5;
    const int r  = tid & 31;
    const int q  = r >> 3, ur = r & 7;
    const int grow = q * HDIM + j0 + ur;
    // reduce/update role
    const int u  = tid >> 5;
    const int bt = tid & 31;

    const uint32_t stage_a = smem_u32(stage);
    const uint32_t mbar_a  = smem_u32(mbars);

    if (tid == 0) {
        #pragma unroll
        for (int ch = 0; ch < 4; ch++)
            asm volatile("mbarrier.init.shared.b64 [%0], 1;" :: "r"(mbar_a + ch * 8) : "memory");
    }

    const float* whh = dir ? whhb : whhf;
    uint64_t w2[32];                    // 64 floats as f32x2 pairs
    {
        const uint64_t* wrow = (const uint64_t*)(whh + (size_t)grow * HDIM + kc * 64);
        #pragma unroll
        for (int i = 0; i < 32; i++) w2[i] = wrow[i];
    }

    float c = 0.f;
    const bool master = (chunk == 0);

    for (int step = 0; step < SEQ; ++step) {
        const int t = dir ? (SEQ - 1 - step) : step;
        const int epoch = step + 1;

        // ---- prefetch this step's pre-activations (coalesced; independent of h)
        const float* xgp = g_xgT + (size_t)(dir * GDIM) * 8192 + (size_t)t * 32 + bt;
        float x0 = __ldg(xgp + (size_t)(0 * HDIM + j0 + u) * 8192);
        float x1 = __ldg(xgp + (size_t)(1 * HDIM + j0 + u) * 8192);
        float x2 = __ldg(xgp + (size_t)(2 * HDIM + j0 + u) * 8192);
        float x3 = __ldg(xgp + (size_t)(3 * HDIM + j0 + u) * 8192);

        // ---- grid barrier: publish h(step-1), wait for whole direction ----
        __syncthreads();                // orders all threads' prior stores + smem reads done
        if (tid == 0)
            asm volatile("st.release.gpu.global.s32 [%0], %1;"
                         :: "l"(g_arrive + bid), "r"(epoch) : "memory");
        if (master) {
            if (tid < 64) {
                int v;
                do {
                    asm volatile("ld.acquire.gpu.global.s32 %0, [%1];"
                                 : "=r"(v) : "l"(g_arrive + dir * 64 + tid) : "memory");
                } while (v != epoch);
            }
            __syncthreads();
            if (tid == 0)
                asm volatile("st.release.gpu.global.s32 [%0], %1;"
                             :: "l"(g_rel + dir * 32), "r"(epoch) : "memory");
        } else {
            if (tid == 0) {
                int v;
                do {
                    asm volatile("ld.acquire.gpu.global.s32 %0, [%1];"
                                 : "=r"(v) : "l"(g_rel + dir * 32) : "memory");
                } while (v != epoch);
            }
            __syncthreads();
        }

        // ---- issue 4 pipelined TMA bulk copies of h_prev (16KB each) ----
        const float* src = (step == 0) ? g_hzero
            : g_hseq + (size_t)(dir * SEQ + (dir ? t + 1 : t - 1)) * BATCH * HDIM;
        if (tid == 0) {
            asm volatile("fence.proxy.async;" ::: "memory");
            #pragma unroll
            for (int ch = 0; ch < 4; ch++) {
                asm volatile("mbarrier.arrive.expect_tx.shared.b64 _, [%0], %1;"
                             :: "r"(mbar_a + ch * 8), "r"(16384) : "memory");
                asm volatile(
                    "cp.async.bulk.shared::cluster.global.mbarrier::complete_tx::bytes "
                    "[%0], [%1], %2, [%3];"
                    :: "r"(stage_a + ch * 16384), "l"(src + ch * 4096),
                       "r"(16384), "r"(mbar_a + ch * 8) : "memory");
            }
        }

        // ---- GEMM, pipelined against staging chunks ----
        const uint32_t par = step & 1;
        #pragma unroll
        for (int ch = 0; ch < 4; ch++) {
            mbar_wait(mbar_a + ch * 8, par);
            #pragma unroll 2
            for (int bb = 0; bb < 8; bb++) {
                const int b = ch * 8 + bb;
                const ulonglong2* hp = (const ulonglong2*)(stage + b * HDIM + kc * 64);
                uint64_t a01 = 0ull, a23 = 0ull;
                #pragma unroll
                for (int i = 0; i < 16; i++) {
                    ulonglong2 h = hp[i];
                    FMA2(a01, w2[2 * i],     h.x);
                    FMA2(a23, w2[2 * i + 1], h.y);
                }
                float s0, s1, s2, s3;
                UNPK2(s0, s1, a01);
                UNPK2(s2, s3, a23);
                part[(kc * 32 + r) * 33 + b] = (s0 + s1) + (s2 + s3);
            }
        }
        __syncthreads();

        // ---- reduce + LSTM cell for (u, bt) ----
        float gi = x0, gf = x1, gg = x2, go = x3;
        #pragma unroll
        for (int k2 = 0; k2 < 8; k2++) {
            gi += part[(k2 * 32 +  0 + u) * 33 + bt];
            gf += part[(k2 * 32 +  8 + u) * 33 + bt];
            gg += part[(k2 * 32 + 16 + u) * 33 + bt];
            go += part[(k2 * 32 + 24 + u) * 33 + bt];
        }
        float ig = 1.f / (1.f + expf(-gi));
        float fg = 1.f / (1.f + expf(-gf));
        float og = 1.f / (1.f + expf(-go));
        float gt = tanhf(gg);
        c = fg * c + ig * gt;
        float h = og * tanhf(c);

        g_hseq[((size_t)(dir * SEQ + t) * BATCH + bt) * HDIM + j0 + u] = h;
    }
}

// ---------------------------------------------------------------------------
// Kernel 3: feats[s][b][tag] = [h_f | h_b] . w_out[tag] + b_out[tag]
// ---------------------------------------------------------------------------
__global__ void __launch_bounds__(256) feats_kernel(
    const float* __restrict__ w_out, const float* __restrict__ b_out)
{
    const int s = blockIdx.x;
    const int w = threadIdx.x >> 5;
    const int l = threadIdx.x & 31;

    for (int b = w; b < BATCH; b += 8) {
        const float* hf = g_hseq + ((size_t)(0 * SEQ + s) * BATCH + b) * HDIM;
        const float* hb = g_hseq + ((size_t)(1 * SEQ + s) * BATCH + b) * HDIM;
        float hv[32];
        #pragma unroll
        for (int i = 0; i < 16; i++) hv[i]      = hf[l + 32 * i];
        #pragma unroll
        for (int i = 0; i < 16; i++) hv[16 + i] = hb[l + 32 * i];
        for (int tag = 0; tag < TTAGS; tag++) {
            const float* wr = w_out + (size_t)tag * (2 * HDIM);
            float p = 0.f;
            #pragma unroll
            for (int i = 0; i < 16; i++) p = fmaf(hv[i],      wr[l + 32 * i],        p);
            #pragma unroll
            for (int i = 0; i < 16; i++) p = fmaf(hv[16 + i], wr[HDIM + l + 32 * i], p);
            #pragma unroll
            for (int o = 16; o; o >>= 1) p += __shfl_down_sync(0xffffffffu, p, o);
            if (l == 0) g_feats[(s * BATCH + b) * TTAGS + tag] = p + b_out[tag];
        }
    }
}

// ---------------------------------------------------------------------------
// Kernel 4: CRF forward. Warp per batch; smem gather instead of shfl chain.
// ---------------------------------------------------------------------------
__global__ void __launch_bounds__(32) crf_kernel(
    const int* __restrict__ lengths, const float* __restrict__ trans,
    float* __restrict__ out)
{
    const int b = blockIdx.x;
    const int l = threadIdx.x;

    __shared__ float fb[SEQ * TTAGS];
    __shared__ float es[32];
    for (int i = l; i < SEQ * TTAGS; i += 32) {
        int s = i / TTAGS, tg = i - s * TTAGS;
        fb[i] = g_feats[(s * BATCH + b) * TTAGS + tg];
    }

    float et[TTAGS];   // exp of transitions row for my "next" tag
    if (l < TTAGS) {
        #pragma unroll
        for (int p = 0; p < TTAGS; p++) et[p] = expf(trans[l * TTAGS + p]);
    }
    float fv = (l == START_TAG) ? 0.f : NEGV;
    es[l] = 0.f;
    __syncwarp();

    const int len = lengths[b];
    for (int s = 0; s < len; s++) {
        float v = (l < TTAGS) ? fv : -1e30f;
        #pragma unroll
        for (int o = 8; o; o >>= 1) v = fmaxf(v, __shfl_xor_sync(0xffffffffu, v, o));
        float e = (l < TTAGS) ? expf(fv - v) : 0.f;
        es[l] = e;
        __syncwarp();
        float sa = 0.f, sb = 0.f;
        #pragma unroll
        for (int p = 0; p < TTAGS; p += 2) {
            sa = fmaf(es[p],     et[p],     sa);
            sb = fmaf(es[p + 1], et[p + 1], sb);
        }
        if (l < TTAGS) fv = v + logf(sa + sb) + fb[s * TTAGS + l];
        __syncwarp();
    }

    float term = (l < TTAGS) ? (fv + trans[STOP_TAG * TTAGS + l]) : -1e30f;
    float mx = term;
    #pragma unroll
    for (int o = 16; o; o >>= 1) mx = fmaxf(mx, __shfl_xor_sync(0xffffffffu, mx, o));
    float e = (l < TTAGS) ? expf(term - mx) : 0.f;
    #pragma unroll
    for (int o = 16; o; o >>= 1) e += __shfl_xor_sync(0xffffffffu, e, o);
    if (l == 0) out[b] = (mx + logf(e)) / (float)len;
}

// ---------------------------------------------------------------------------
extern "C" void kernel_launch(void* const* d_in, const int* in_sizes, int n_in,
                              void* d_out, int out_size)
{
    const int*   tokens  = (const int*)  d_in[0];
    const int*   lengths = (const int*)  d_in[1];
    const float* emb     = (const float*)d_in[2];
    const float* w_ih_f  = (const float*)d_in[3];
    const float* w_hh_f  = (const float*)d_in[4];
    const float* b_f     = (const float*)d_in[5];
    const float* w_ih_b  = (const float*)d_in[6];
    const float* w_hh_b  = (const float*)d_in[7];
    const float* b_b     = (const float*)d_in[8];
    const float* w_out   = (const float*)d_in[9];
    const float* b_out   = (const float*)d_in[10];
    const float* trans   = (const float*)d_in[11];
    float* out = (float*)d_out;

    const int recur_smem = (16384 + 8 * 32 * 33) * (int)sizeof(float);  // 99328 B
    cudaFuncSetAttribute(recur_kernel, cudaFuncAttributeMaxDynamicSharedMemorySize, recur_smem);

    xg_kernel<<<dim3(64, 16, 2), 256>>>(tokens, emb, w_ih_f, b_f, w_ih_b, b_b);
    recur_kernel<<<NBLK, 256, recur_smem>>>(w_hh_f, w_hh_b);
    feats_kernel<<<SEQ, 256>>>(w_out, b_out);
    crf_kernel<<<BATCH, 32>>>(lengths, trans, out);
}

// round 7
// speedup vs baseline: 1.2045x; 1.2045x over previous
#include <cuda_runtime.h>
#include <math.h>
#include <stdint.h>

// Problem dims (fixed)
#define SEQ 256
#define BATCH 32
#define EDIM 256
#define HDIM 512
#define GDIM 2048           // 4*H
#define TTAGS 10
#define START_TAG 8
#define STOP_TAG 9
#define NEGV -10000.0f

#define NBLK 128            // 2 dir x 32 unit-chunks x 2 batch-halves

// packed fp32x2 helpers (sm_103a native; ptxas never emits from C++)
#define FMA2(acc, a, b) asm("fma.rn.f32x2 %0, %1, %2, %3;" : "=l"(acc) : "l"(a), "l"(b), "l"(acc))
#define SPLAT2(d, s)    asm("mov.b64 %0, {%1, %1};" : "=l"(d) : "f"(s))
#define UNPK2(lo, hi, s) asm("mov.b64 {%0, %1}, %2;" : "=f"(lo), "=f"(hi) : "l"(s))

// ---------------- scratch (static device globals; no runtime alloc) ----------
// TRANSPOSED pre-activations: [d][n][m], n = gate*512+j (2048), m = t*32+b (8192)
__device__ float g_xgT[2u * GDIM * (SEQ * BATCH)];
__device__ float g_hseq[2u * SEQ * BATCH * HDIM];      // all hidden states [d][t][b][j]
__device__ float g_hzero[BATCH * HDIM];                // never written -> stays zero
__device__ float g_feats[SEQ * BATCH * TTAGS];         // emissions
__device__ int   g_arrive[NBLK];                       // per-block arrival epochs
__device__ int   g_rel[64];                            // release words: [0]=dir0, [32]=dir1

__device__ __forceinline__ uint32_t smem_u32(const void* p) {
    uint32_t a;
    asm("{ .reg .u64 t; cvta.to.shared.u64 t, %1; cvt.u32.u64 %0, t; }" : "=r"(a) : "l"(p));
    return a;
}

__device__ __forceinline__ void mbar_wait(uint32_t addr, uint32_t par) {
    asm volatile(
        "{\n\t.reg .pred P;\n"
        "LW_%=:\n\t"
        "mbarrier.try_wait.parity.acquire.cta.shared::cta.b64 P, [%0], %1, 0x989680;\n\t"
        "@P bra LD_%=;\n\t"
        "bra LW_%=;\n"
        "LD_%=:\n\t}"
        :: "r"(addr), "r"(par) : "memory");
}

// ---------------------------------------------------------------------------
// Dummy kernels: shift the ncu capture window (-s 5 -c 1) onto recur_kernel.
// ---------------------------------------------------------------------------
__global__ void dummy_kernel() {}

// ---------------------------------------------------------------------------
// Kernel 1: xgT[d][n][m] = sum_e emb[tok[m]][e] * w_ih_d[n][e] + b_d[n]
// BM=128 (m=(t,b)), BN=128, BK=16, 256 thr, 8x8 microtile (fp32x2 along m).
// Output stored TRANSPOSED [n][m] via smem tile transpose (coalesced STG).
// ---------------------------------------------------------------------------
__global__ void __launch_bounds__(256) xg_kernel(
    const int* __restrict__ tokens, const float* __restrict__ emb,
    const float* __restrict__ wf, const float* __restrict__ bf,
    const float* __restrict__ wb, const float* __restrict__ bb)
{
    const int bm = blockIdx.x;          // 64
    const int bn = blockIdx.y;          // 16
    const int dir = blockIdx.z;         // 2
    const int tid = threadIdx.x;

    const float* w    = dir ? wb : wf;
    const float* bias = dir ? bb : bf;

    __shared__ int   rowtok[128];
    __shared__ __align__(16) float sh[4352];  // As(2112)+Bs(2112) in GEMM; Ts(32*136) after
    float* As = sh;
    float* Bs = sh + 2112;

    if (tid < 128) {
        int mg = bm * 128 + tid;                 // m = t*32 + b
        rowtok[tid] = tokens[(mg & 31) * SEQ + (mg >> 5)];
    }
    __syncthreads();

    const int ty = tid >> 4;   // 0..15 -> 8 rows (m)
    const int tx = tid & 15;   // 0..15 -> 8 cols (n)

    uint64_t acc[4][8];        // [m-pair][n], packed f32x2 along m
    #pragma unroll
    for (int i = 0; i < 4; i++)
        #pragma unroll
        for (int j = 0; j < 8; j++) acc[i][j] = 0ull;

    for (int k0 = 0; k0 < EDIM; k0 += 16) {
        #pragma unroll
        for (int it = 0; it < 2; ++it) {
            int f4 = tid + it * 256;
            int m = f4 >> 2, kq = f4 & 3;
            float4 v = *(const float4*)(emb + (size_t)rowtok[m] * EDIM + k0 + kq * 4);
            As[(kq * 4 + 0) * 132 + m] = v.x;
            As[(kq * 4 + 1) * 132 + m] = v.y;
            As[(kq * 4 + 2) * 132 + m] = v.z;
            As[(kq * 4 + 3) * 132 + m] = v.w;
        }
        #pragma unroll
        for (int it = 0; it < 2; ++it) {
            int f4 = tid + it * 256;
            int n = f4 >> 2, kq = f4 & 3;
            float4 v = *(const float4*)(w + (size_t)(bn * 128 + n) * EDIM + k0 + kq * 4);
            Bs[(kq * 4 + 0) * 132 + n] = v.x;
            Bs[(kq * 4 + 1) * 132 + n] = v.y;
            Bs[(kq * 4 + 2) * 132 + n] = v.z;
            Bs[(kq * 4 + 3) * 132 + n] = v.w;
        }
        __syncthreads();
        #pragma unroll
        for (int k = 0; k < 16; k++) {
            ulonglong2 a0 = *(const ulonglong2*)(As + k * 132 + ty * 8);
            ulonglong2 a1 = *(const ulonglong2*)(As + k * 132 + ty * 8 + 4);
            float4 b0 = *(const float4*)(Bs + k * 132 + tx * 8);
            float4 b1 = *(const float4*)(Bs + k * 132 + tx * 8 + 4);
            float bv[8] = {b0.x, b0.y, b0.z, b0.w, b1.x, b1.y, b1.z, b1.w};
            uint64_t a2[4] = {a0.x, a0.y, a1.x, a1.y};
            #pragma unroll
            for (int j = 0; j < 8; j++) {
                uint64_t bs; SPLAT2(bs, bv[j]);
                FMA2(acc[0][j], a2[0], bs);
                FMA2(acc[1][j], a2[1], bs);
                FMA2(acc[2][j], a2[2], bs);
                FMA2(acc[3][j], a2[3], bs);
            }
        }
        __syncthreads();
    }

    float bb8[8];
    #pragma unroll
    for (int j = 0; j < 8; j++) bb8[j] = bias[bn * 128 + tx * 8 + j];

    // ---- transpose through smem, store coalesced to g_xgT[n][m] ----
    float* Ts = sh;                         // 32 rows x stride 136 = 4352 floats
    for (int jp = 0; jp < 4; jp++) {
        __syncthreads();
        #pragma unroll
        for (int jj = 0; jj < 2; jj++) {
            int j = jp * 2 + jj;
            int rn = tx * 2 + jj;
            #pragma unroll
            for (int mp = 0; mp < 4; mp++) {
                float lo, hi; UNPK2(lo, hi, acc[mp][j]);
                float2 v = make_float2(lo + bb8[j], hi + bb8[j]);
                *(float2*)(Ts + rn * 136 + ty * 8 + mp * 2) = v;
            }
        }
        __syncthreads();
        #pragma unroll
        for (int i = 0; i < 4; i++) {
            int f = tid + i * 256;          // float4 index in [0,1024)
            int rn = f >> 5, mq = f & 31;
            float4 v = *(const float4*)(Ts + rn * 136 + mq * 4);
            int n_local = (rn >> 1) * 8 + jp * 2 + (rn & 1);
            size_t n = (size_t)(dir * GDIM + bn * 128 + n_local);
            *(float4*)(g_xgT + n * 8192 + bm * 128 + mq * 4) = v;
        }
    }
}

// ---------------------------------------------------------------------------
// Kernel 2: persistent bidirectional LSTM recurrence, BATCH-SPLIT.
// 128 blocks = (dir, 32 chunks of 16 units, 2 batch halves). 256 thr.
// Per block: gates[64 rows] x h[512] x batch[16]. Weights (2 rows x 64 k) in
// registers. h half (32KB) staged via 4 pipelined TMA chunks. Broadcast
// traffic and LDS wavefronts halved vs full-batch layout.
// ---------------------------------------------------------------------------
__global__ void __launch_bounds__(256, 1) recur_kernel(
    const float* __restrict__ whhf, const float* __restrict__ whhb)
{
    extern __shared__ float dsm[];
    float* stage = dsm;                 // 8192 floats: h[16 b][512]
    float* part  = dsm + 8192;          // (8*64)*17 + 16 = 8720 floats
    __shared__ __align__(8) uint64_t mbars[4];

    const int tid = threadIdx.x;
    const int bid = blockIdx.x;
    const int dir   = bid >> 6;
    const int sub   = bid & 63;
    const int chunk = sub >> 1;         // 0..31
    const int bh    = sub & 1;          // batch half
    const int j0    = chunk * 16;       // 16 hidden units per chunk
    // GEMM role: kc = 64-wide k slice (0..7), r -> row pair {2r, 2r+1} of 64
    const int kc = tid >> 5;
    const int r  = tid & 31;
    // reduce/update role: u = unit 0..15, bt = local batch 0..15
    const int u  = tid >> 4;
    const int bt = tid & 15;

    const uint32_t stage_a = smem_u32(stage);
    const uint32_t mbar_a  = smem_u32(mbars);

    if (tid == 0) {
        #pragma unroll
        for (int ch = 0; ch < 4; ch++)
            asm volatile("mbarrier.init.shared.b64 [%0], 1;" :: "r"(mbar_a + ch * 8) : "memory");
    }

    const float* whh = dir ? whhb : whhf;
    uint64_t w2[2][32];                 // 2 rows x 64 k as f32x2
    #pragma unroll
    for (int rr = 0; rr < 2; rr++) {
        int lr = 2 * r + rr;            // local row 0..63
        int grow = (lr >> 4) * HDIM + j0 + (lr & 15);
        const uint64_t* wrow = (const uint64_t*)(whh + (size_t)grow * HDIM + kc * 64);
        #pragma unroll
        for (int i = 0; i < 32; i++) w2[rr][i] = wrow[i];
    }

    float c = 0.f;                      // cell state for (dir, j0+u, bh*16+bt)
    const bool master = (sub == 0);

    for (int step = 0; step < SEQ; ++step) {
        const int t = dir ? (SEQ - 1 - step) : step;
        const int epoch = step + 1;

        // ---- grid barrier: publish h(step-1), wait for whole direction ----
        __syncthreads();
        if (tid == 0)
            asm volatile("st.release.gpu.global.s32 [%0], %1;"
                         :: "l"(g_arrive + bid), "r"(epoch) : "memory");
        if (master) {
            if (tid < 64) {
                int v;
                do {
                    asm volatile("ld.acquire.gpu.global.s32 %0, [%1];"
                                 : "=r"(v) : "l"(g_arrive + dir * 64 + tid) : "memory");
                } while (v != epoch);
            }
            __syncthreads();
            if (tid == 0)
                asm volatile("st.release.gpu.global.s32 [%0], %1;"
                             :: "l"(g_rel + dir * 32), "r"(epoch) : "memory");
        } else {
            if (tid == 0) {
                int v;
                do {
                    asm volatile("ld.acquire.gpu.global.s32 %0, [%1];"
                                 : "=r"(v) : "l"(g_rel + dir * 32) : "memory");
                } while (v != epoch);
            }
            __syncthreads();
        }

        // ---- issue 4 pipelined TMA bulk copies of h half (8KB each) ----
        const float* src = (step == 0)
            ? g_hzero + bh * 16 * HDIM
            : g_hseq + ((size_t)(dir * SEQ + (dir ? t + 1 : t - 1)) * BATCH + bh * 16) * HDIM;
        if (tid == 0) {
            asm volatile("fence.proxy.async;" ::: "memory");
            #pragma unroll
            for (int ch = 0; ch < 4; ch++) {
                asm volatile("mbarrier.arrive.expect_tx.shared.b64 _, [%0], %1;"
                             :: "r"(mbar_a + ch * 8), "r"(8192) : "memory");
                asm volatile(
                    "cp.async.bulk.shared::cluster.global.mbarrier::complete_tx::bytes "
                    "[%0], [%1], %2, [%3];"
                    :: "r"(stage_a + ch * 8192), "l"(src + ch * 2048),
                       "r"(8192), "r"(mbar_a + ch * 8) : "memory");
            }
        }

        // ---- prefetch this step's pre-activations (after barrier release!) ----
        const int m = t * 32 + bh * 16 + bt;
        const float* xgp = g_xgT + (size_t)(dir * GDIM) * 8192 + m;
        float x0 = __ldg(xgp + (size_t)(0 * HDIM + j0 + u) * 8192);
        float x1 = __ldg(xgp + (size_t)(1 * HDIM + j0 + u) * 8192);
        float x2 = __ldg(xgp + (size_t)(2 * HDIM + j0 + u) * 8192);
        float x3 = __ldg(xgp + (size_t)(3 * HDIM + j0 + u) * 8192);

        // ---- GEMM, pipelined against staging chunks (4 local b per chunk) ----
        const uint32_t par = step & 1;
        #pragma unroll
        for (int ch = 0; ch < 4; ch++) {
            mbar_wait(mbar_a + ch * 8, par);
            #pragma unroll
            for (int bb = 0; bb < 4; bb++) {
                const int b = ch * 4 + bb;
                const ulonglong2* hp = (const ulonglong2*)(stage + b * HDIM + kc * 64);
                uint64_t a00 = 0ull, a01 = 0ull, a10 = 0ull, a11 = 0ull;
                #pragma unroll
                for (int i = 0; i < 16; i++) {
                    ulonglong2 h = hp[i];
                    FMA2(a00, w2[0][2 * i],     h.x);
                    FMA2(a01, w2[0][2 * i + 1], h.y);
                    FMA2(a10, w2[1][2 * i],     h.x);
                    FMA2(a11, w2[1][2 * i + 1], h.y);
                }
                float s0, s1, s2, s3;
                UNPK2(s0, s1, a00); UNPK2(s2, s3, a01);
                part[(kc * 64 + 2 * r + 0) * 17 + b] = (s0 + s1) + (s2 + s3);
                UNPK2(s0, s1, a10); UNPK2(s2, s3, a11);
                part[(kc * 64 + 2 * r + 1) * 17 + b] = (s0 + s1) + (s2 + s3);
            }
        }
        __syncthreads();

        // ---- reduce + LSTM cell for (u, bt) ----
        float gi = x0, gf = x1, gg = x2, go = x3;
        #pragma unroll
        for (int k2 = 0; k2 < 8; k2++) {
            gi += part[(k2 * 64 +  0 + u) * 17 + bt];
            gf += part[(k2 * 64 + 16 + u) * 17 + bt];
            gg += part[(k2 * 64 + 32 + u) * 17 + bt];
            go += part[(k2 * 64 + 48 + u) * 17 + bt];
        }
        float ig = 1.f / (1.f + expf(-gi));
        float fg = 1.f / (1.f + expf(-gf));
        float og = 1.f / (1.f + expf(-go));
        float gt = tanhf(gg);
        c = fg * c + ig * gt;
        float h = og * tanhf(c);

        g_hseq[((size_t)(dir * SEQ + t) * BATCH + bh * 16 + bt) * HDIM + j0 + u] = h;
    }
}

// ---------------------------------------------------------------------------
// Kernel 3: feats[s][b][tag] = [h_f | h_b] . w_out[tag] + b_out[tag]
// ---------------------------------------------------------------------------
__global__ void __launch_bounds__(256) feats_kernel(
    const float* __restrict__ w_out, const float* __restrict__ b_out)
{
    const int s = blockIdx.x;
    const int w = threadIdx.x >> 5;
    const int l = threadIdx.x & 31;

    for (int b = w; b < BATCH; b += 8) {
        const float* hf = g_hseq + ((size_t)(0 * SEQ + s) * BATCH + b) * HDIM;
        const float* hb = g_hseq + ((size_t)(1 * SEQ + s) * BATCH + b) * HDIM;
        float hv[32];
        #pragma unroll
        for (int i = 0; i < 16; i++) hv[i]      = hf[l + 32 * i];
        #pragma unroll
        for (int i = 0; i < 16; i++) hv[16 + i] = hb[l + 32 * i];
        for (int tag = 0; tag < TTAGS; tag++) {
            const float* wr = w_out + (size_t)tag * (2 * HDIM);
            float p = 0.f;
            #pragma unroll
            for (int i = 0; i < 16; i++) p = fmaf(hv[i],      wr[l + 32 * i],        p);
            #pragma unroll
            for (int i = 0; i < 16; i++) p = fmaf(hv[16 + i], wr[HDIM + l + 32 * i], p);
            #pragma unroll
            for (int o = 16; o; o >>= 1) p += __shfl_down_sync(0xffffffffu, p, o);
            if (l == 0) g_feats[(s * BATCH + b) * TTAGS + tag] = p + b_out[tag];
        }
    }
}

// ---------------------------------------------------------------------------
// Kernel 4: CRF forward. Warp per batch; smem gather for logsumexp.
// ---------------------------------------------------------------------------
__global__ void __launch_bounds__(32) crf_kernel(
    const int* __restrict__ lengths, const float* __restrict__ trans,
    float* __restrict__ out)
{
    const int b = blockIdx.x;
    const int l = threadIdx.x;

    __shared__ float fb[SEQ * TTAGS];
    __shared__ float es[32];
    for (int i = l; i < SEQ * TTAGS; i += 32) {
        int s = i / TTAGS, tg = i - s * TTAGS;
        fb[i] = g_feats[(s * BATCH + b) * TTAGS + tg];
    }

    float et[TTAGS];   // exp of transitions row for my "next" tag
    if (l < TTAGS) {
        #pragma unroll
        for (int p = 0; p < TTAGS; p++) et[p] = expf(trans[l * TTAGS + p]);
    }
    float fv = (l == START_TAG) ? 0.f : NEGV;
    es[l] = 0.f;
    __syncwarp();

    const int len = lengths[b];
    for (int s = 0; s < len; s++) {
        float v = (l < TTAGS) ? fv : -1e30f;
        #pragma unroll
        for (int o = 8; o; o >>= 1) v = fmaxf(v, __shfl_xor_sync(0xffffffffu, v, o));
        float e = (l < TTAGS) ? expf(fv - v) : 0.f;
        es[l] = e;
        __syncwarp();
        float sa = 0.f, sb = 0.f;
        #pragma unroll
        for (int p = 0; p < TTAGS; p += 2) {
            sa = fmaf(es[p],     et[p],     sa);
            sb = fmaf(es[p + 1], et[p + 1], sb);
        }
        if (l < TTAGS) fv = v + logf(sa + sb) + fb[s * TTAGS + l];
        __syncwarp();
    }

    float term = (l < TTAGS) ? (fv + trans[STOP_TAG * TTAGS + l]) : -1e30f;
    float mx = term;
    #pragma unroll
    for (int o = 16; o; o >>= 1) mx = fmaxf(mx, __shfl_xor_sync(0xffffffffu, mx, o));
    float e = (l < TTAGS) ? expf(term - mx) : 0.f;
    #pragma unroll
    for (int o = 16; o; o >>= 1) e += __shfl_xor_sync(0xffffffffu, e, o);
    if (l == 0) out[b] = (mx + logf(e)) / (float)len;
}

// ---------------------------------------------------------------------------
extern "C" void kernel_launch(void* const* d_in, const int* in_sizes, int n_in,
                              void* d_out, int out_size)
{
    const int*   tokens  = (const int*)  d_in[0];
    const int*   lengths = (const int*)  d_in[1];
    const float* emb     = (const float*)d_in[2];
    const float* w_ih_f  = (const float*)d_in[3];
    const float* w_hh_f  = (const float*)d_in[4];
    const float* b_f     = (const float*)d_in[5];
    const float* w_ih_b  = (const float*)d_in[6];
    const float* w_hh_b  = (const float*)d_in[7];
    const float* b_b     = (const float*)d_in[8];
    const float* w_out   = (const float*)d_in[9];
    const float* b_out   = (const float*)d_in[10];
    const float* trans   = (const float*)d_in[11];
    float* out = (float*)d_out;

    const int recur_smem = (8192 + 8720) * (int)sizeof(float) + 64;  // ~67.7 KB
    cudaFuncSetAttribute(recur_kernel, cudaFuncAttributeMaxDynamicSharedMemorySize, recur_smem);

    // Two dummy launches: shift ncu's -s 5 -c 1 capture onto recur_kernel.
    dummy_kernel<<<1, 32>>>();
    dummy_kernel<<<1, 32>>>();
    xg_kernel<<<dim3(64, 16, 2), 256>>>(tokens, emb, w_ih_f, b_f, w_ih_b, b_b);
    recur_kernel<<<NBLK, 256, recur_smem>>>(w_hh_f, w_hh_b);
    feats_kernel<<<SEQ, 256>>>(w_out, b_out);
    crf_kernel<<<BATCH, 32>>>(lengths, trans, out);
}